// round 1
// baseline (speedup 1.0000x reference)
#include <cuda_runtime.h>
#include <math.h>

#define NN 5000
#define NE 60000
#define NT 400000

// ---------------- scratch (device globals; no allocations allowed) -------------
__device__ float g_bondvec[NE * 3];
__device__ float g_dist[NE];
__device__ float g_rbf[NE * 9];
__device__ float g_cut3[NE];
__device__ float g_tbw[NT * 9];      // three_basis * tw
__device__ int   g_endatom[NT];
__device__ float g_nodefeat[NN * 128];
__device__ float g_edgefeat[NE * 128];
__device__ float g_atoms[NN * 9];
__device__ float g_nb[NE * 9];
__device__ float g_x[NE * 384];
__device__ float g_h[NE * 128];
__device__ float g_g[NE * 128];
__device__ float g_t[NE * 128];
__device__ float g_scale[9];

__constant__ float c_roots[9] = {
    3.141592653589793f, 6.283185307179586f, 9.42477796076938f,
    4.493409457909064f, 7.725251836937707f, 10.904121659428899f,
    5.763459196894550f, 9.095011330476355f, 12.322940970566582f};

#define Y00F 0.28209479177387814f
#define Y10F 0.4886025119029199f
#define Y20F 0.31539156525252005f

__device__ __forceinline__ float siluf(float v) { return v / (1.f + expf(-v)); }
__device__ __forceinline__ float sigf(float v)  { return 1.f / (1.f + expf(-v)); }

__device__ __forceinline__ float jlf(int l, float x) {
    float s, c;
    sincosf(x, &s, &c);
    float inv = 1.f / x;
    if (l == 0) return s * inv;
    if (l == 1) return (s * inv - c) * inv;
    return (3.f * inv * inv - 1.f) * s * inv - 3.f * c * inv * inv;
}

__device__ double jld(int l, double x) {
    double s = sin(x), c = cos(x);
    if (l == 0) return s / x;
    if (l == 1) return s / (x * x) - c / x;
    if (l == 2) return (3.0 / (x * x * x) - 1.0 / x) * s - 3.0 * c / (x * x);
    return (15.0 / (x * x * x * x) - 6.0 / (x * x)) * s - (15.0 / (x * x * x) - 1.0 / x) * c;
}

// ---------------- setup kernels ------------------------------------------------
__global__ void k_init_scales() {
    if (threadIdx.x == 0 && blockIdx.x == 0) {
        const double roots[9] = {
            3.141592653589793, 6.283185307179586, 9.42477796076938,
            4.493409457909064, 7.725251836937707, 10.904121659428899,
            5.763459196894550, 9.095011330476355, 12.322940970566582};
        double fac = sqrt(2.0 / 125.0);  // sqrt(2/CUTOFF^3), CUTOFF=5
        for (int l = 0; l < 3; l++)
            for (int n = 0; n < 3; n++) {
                double norm = fabs(jld(l + 1, roots[l * 3 + n]));
                g_scale[l * 3 + n] = (float)(fac / norm);
            }
    }
}

__global__ void k_geom(const float* __restrict__ pos, const int* __restrict__ src,
                       const int* __restrict__ dst) {
    int e = blockIdx.x * blockDim.x + threadIdx.x;
    if (e >= NE) return;
    int s = src[e], d = dst[e];
    float dx = pos[d * 3 + 0] - pos[s * 3 + 0];
    float dy = pos[d * 3 + 1] - pos[s * 3 + 1];
    float dz = pos[d * 3 + 2] - pos[s * 3 + 2];
    float dist = sqrtf(dx * dx + dy * dy + dz * dz + 1e-12f);
    g_bondvec[e * 3 + 0] = dx;
    g_bondvec[e * 3 + 1] = dy;
    g_bondvec[e * 3 + 2] = dz;
    g_dist[e] = dist;
#pragma unroll
    for (int l = 0; l < 3; l++)
#pragma unroll
        for (int n = 0; n < 3; n++)
            g_rbf[e * 9 + l * 3 + n] = jlf(l, dist * c_roots[l * 3 + n] * 0.2f) * g_scale[l * 3 + n];
    float xx = dist * 0.25f;  // /TB_CUTOFF
    float x2 = xx * xx, x3 = x2 * xx;
    g_cut3[e] = 1.f - 6.f * x3 * x2 + 15.f * x2 * x2 - 10.f * x3;
}

__global__ void k_triplet(const int* __restrict__ t_src, const int* __restrict__ t_dst,
                          const int* __restrict__ dst) {
    int t = blockIdx.x * blockDim.x + threadIdx.x;
    if (t >= NT) return;
    int es = t_src[t], ed = t_dst[t];
    float v1x = g_bondvec[es * 3 + 0], v1y = g_bondvec[es * 3 + 1], v1z = g_bondvec[es * 3 + 2];
    float v2x = g_bondvec[ed * 3 + 0], v2y = g_bondvec[ed * 3 + 1], v2z = g_bondvec[ed * 3 + 2];
    float d1 = g_dist[es], d2 = g_dist[ed];
    float cost = (v1x * v2x + v1y * v2y + v1z * v2z) / (d1 * d2);
    float shf[3];
    shf[0] = Y00F;
    shf[1] = Y10F * cost;
    shf[2] = Y20F * (3.f * cost * cost - 1.f);
    float tw = g_cut3[es] * g_cut3[ed];
#pragma unroll
    for (int l = 0; l < 3; l++)
#pragma unroll
        for (int n = 0; n < 3; n++) {
            float v = jlf(l, d2 * c_roots[l * 3 + n] * 0.2f) * g_scale[l * 3 + n];
            g_tbw[t * 9 + l * 3 + n] = v * shf[l] * tw;
        }
    g_endatom[t] = dst[ed];
}

__global__ void k_nodeinit(const int* __restrict__ node_type, const float* __restrict__ emb) {
    int idx = blockIdx.x * blockDim.x + threadIdx.x;
    if (idx >= NN * 128) return;
    int n = idx >> 7, c = idx & 127;
    g_nodefeat[idx] = emb[node_type[n] * 128 + c];
}

__global__ void k_edgeemb(const float* __restrict__ W, const float* __restrict__ b) {
    int idx = blockIdx.x * blockDim.x + threadIdx.x;
    if (idx >= NE * 128) return;
    int e = idx >> 7, j = idx & 127;
    float acc = b[j];
#pragma unroll
    for (int q = 0; q < 9; q++) acc = fmaf(g_rbf[e * 9 + q], W[q * 128 + j], acc);
    g_edgefeat[idx] = siluf(acc);
}

// ---------------- per-block kernels --------------------------------------------
__global__ void k_atoms(const float* __restrict__ W, const float* __restrict__ b) {
    int idx = blockIdx.x * blockDim.x + threadIdx.x;
    if (idx >= NN * 9) return;
    int n = idx / 9, j = idx % 9;
    float acc = b[j];
    const float* nf = &g_nodefeat[n * 128];
#pragma unroll 8
    for (int i = 0; i < 128; i++) acc = fmaf(nf[i], W[i * 9 + j], acc);
    g_atoms[idx] = sigf(acc);
}

__global__ void k_zero_nb() {
    int idx = blockIdx.x * blockDim.x + threadIdx.x;
    if (idx < NE * 9) g_nb[idx] = 0.f;
}

__global__ void k_tripacc(const int* __restrict__ t_src) {
    int t = blockIdx.x * blockDim.x + threadIdx.x;
    if (t >= NT) return;
    int es = t_src[t];
    int ea = g_endatom[t];
#pragma unroll
    for (int q = 0; q < 9; q++)
        atomicAdd(&g_nb[es * 9 + q], g_tbw[t * 9 + q] * g_atoms[ea * 9 + q]);
}

__global__ void k_tbond(const float* __restrict__ Wb, const float* __restrict__ Wg) {
    int idx = blockIdx.x * blockDim.x + threadIdx.x;
    if (idx >= NE * 128) return;
    int e = idx >> 7, j = idx & 127;
    float s1 = 0.f, s2 = 0.f;
#pragma unroll
    for (int q = 0; q < 9; q++) {
        float nv = g_nb[e * 9 + q];
        s1 = fmaf(nv, Wb[q * 128 + j], s1);
        s2 = fmaf(nv, Wg[q * 128 + j], s2);
    }
    g_edgefeat[idx] += siluf(s1) * sigf(s2);
}

__global__ void k_buildx(const int* __restrict__ src, const int* __restrict__ dst) {
    int idx = blockIdx.x * blockDim.x + threadIdx.x;
    if (idx >= NE * 384) return;
    int e = idx / 384, c = idx % 384;
    float v;
    if (c < 128)      v = g_nodefeat[src[e] * 128 + c];
    else if (c < 256) v = g_nodefeat[dst[e] * 128 + (c - 128)];
    else              v = g_edgefeat[e * 128 + (c - 256)];
    g_x[idx] = v;
}

__global__ void k_combine_edge(const float* __restrict__ wt) {
    int idx = blockIdx.x * blockDim.x + threadIdx.x;
    if (idx >= NE * 128) return;
    int e = idx >> 7, j = idx & 127;
    float w = 0.f;
#pragma unroll
    for (int q = 0; q < 9; q++) w = fmaf(g_rbf[e * 9 + q], wt[q * 128 + j], w);
    float v = g_edgefeat[idx] + g_h[idx] * g_g[idx] * w;
    g_edgefeat[idx] = v;
    g_x[e * 384 + 256 + j] = v;
}

__global__ void k_combine_node(const float* __restrict__ wt, const int* __restrict__ dst) {
    int idx = blockIdx.x * blockDim.x + threadIdx.x;
    if (idx >= NE * 128) return;
    int e = idx >> 7, j = idx & 127;
    float w = 0.f;
#pragma unroll
    for (int q = 0; q < 9; q++) w = fmaf(g_rbf[e * 9 + q], wt[q * 128 + j], w);
    float m = g_h[idx] * g_g[idx] * w;
    atomicAdd(&g_nodefeat[dst[e] * 128 + j], m);
}

// ---------------- tiled fp32 GEMM: C[M,N] = act(A[M,K] @ B[K,N] + bias) --------
#define BM 64
#define BN 64
#define BK 16
__global__ void gemm_act_kernel(const float* __restrict__ A, const float* __restrict__ B,
                                const float* __restrict__ bias, float* __restrict__ C,
                                int M, int K, int N, int act) {
    __shared__ float As[BM][BK + 1];
    __shared__ float Bs[BK][BN];
    int bm = blockIdx.y * BM;
    int bn = blockIdx.x * BN;
    int tid = threadIdx.x;
    int tx = tid & 15;   // col group
    int ty = tid >> 4;   // row group
    float acc[4][4];
#pragma unroll
    for (int i = 0; i < 4; i++)
#pragma unroll
        for (int j = 0; j < 4; j++) acc[i][j] = 0.f;

    for (int k0 = 0; k0 < K; k0 += BK) {
#pragma unroll
        for (int i = 0; i < 4; i++) {
            int idx = tid + i * 256;
            int m = idx >> 4, kk = idx & 15;
            int gm = bm + m;
            As[m][kk] = (gm < M) ? A[(size_t)gm * K + k0 + kk] : 0.f;
        }
#pragma unroll
        for (int i = 0; i < 4; i++) {
            int idx = tid + i * 256;
            int kk = idx >> 6, n = idx & 63;
            Bs[kk][n] = B[(size_t)(k0 + kk) * N + bn + n];
        }
        __syncthreads();
#pragma unroll
        for (int kk = 0; kk < BK; kk++) {
            float a[4], b[4];
#pragma unroll
            for (int i = 0; i < 4; i++) a[i] = As[ty + i * 16][kk];
#pragma unroll
            for (int j = 0; j < 4; j++) b[j] = Bs[kk][tx + j * 16];
#pragma unroll
            for (int i = 0; i < 4; i++)
#pragma unroll
                for (int j = 0; j < 4; j++) acc[i][j] = fmaf(a[i], b[j], acc[i][j]);
        }
        __syncthreads();
    }
#pragma unroll
    for (int i = 0; i < 4; i++) {
        int gm = bm + ty + i * 16;
        if (gm >= M) continue;
#pragma unroll
        for (int j = 0; j < 4; j++) {
            int gn = bn + tx + j * 16;
            float v = acc[i][j] + bias[gn];
            v = (act == 0) ? siluf(v) : sigf(v);
            C[(size_t)gm * N + gn] = v;
        }
    }
}

// ---------------- final readout ------------------------------------------------
__global__ void k_final(const float* __restrict__ fW0, const float* __restrict__ fb0,
                        const float* __restrict__ fW1, const float* __restrict__ fb1,
                        const float* __restrict__ fW2, const float* __restrict__ fb2,
                        float* __restrict__ out) {
    __shared__ float v[128], h0[128], h1[128], red[128];
    int j = threadIdx.x;
    float s = 0.f;
    for (int n = 0; n < NN; n++) s += g_nodefeat[n * 128 + j];
    v[j] = s / (float)NN;
    __syncthreads();
    float a = fb0[j];
    for (int i = 0; i < 128; i++) a = fmaf(v[i], fW0[i * 128 + j], a);
    h0[j] = siluf(a);
    __syncthreads();
    a = fb1[j];
    for (int i = 0; i < 128; i++) a = fmaf(h0[i], fW1[i * 128 + j], a);
    h1[j] = siluf(a);
    __syncthreads();
    red[j] = h1[j] * fW2[j];
    __syncthreads();
    for (int st = 64; st > 0; st >>= 1) {
        if (j < st) red[j] += red[j + st];
        __syncthreads();
    }
    if (j == 0) out[0] = red[0] + fb2[0];
}

// ---------------- host ----------------------------------------------------------
static void gemm(const float* A, const float* B, const float* bias, float* C,
                 int M, int K, int N, int act) {
    dim3 grid(N / BN, (M + BM - 1) / BM);
    gemm_act_kernel<<<grid, 256>>>(A, B, bias, C, M, K, N, act);
}

extern "C" void kernel_launch(void* const* d_in, const int* in_sizes, int n_in,
                              void* d_out, int out_size) {
    const float* pos  = (const float*)d_in[0];
    const int* node_type = (const int*)d_in[1];
    const int* src  = (const int*)d_in[2];
    const int* dst  = (const int*)d_in[3];
    const int* t_src = (const int*)d_in[4];
    const int* t_dst = (const int*)d_in[5];
    const float* emb  = (const float*)d_in[6];
    const float* eW   = (const float*)d_in[7];
    const float* eb   = (const float*)d_in[8];
    const float* taW  = (const float*)d_in[9];
    const float* tab  = (const float*)d_in[10];
    const float* tbW  = (const float*)d_in[11];
    const float* tbWg = (const float*)d_in[12];
    const float* W0 = (const float*)d_in[13];  const float* b0 = (const float*)d_in[14];
    const float* W1 = (const float*)d_in[15];  const float* b1 = (const float*)d_in[16];
    const float* W2 = (const float*)d_in[17];  const float* b2 = (const float*)d_in[18];
    const float* gW0 = (const float*)d_in[19]; const float* gb0 = (const float*)d_in[20];
    const float* gW1 = (const float*)d_in[21]; const float* gb1 = (const float*)d_in[22];
    const float* gW2 = (const float*)d_in[23]; const float* gb2 = (const float*)d_in[24];
    const float* wt = (const float*)d_in[25];
    const float* fW0 = (const float*)d_in[26]; const float* fb0 = (const float*)d_in[27];
    const float* fW1 = (const float*)d_in[28]; const float* fb1 = (const float*)d_in[29];
    const float* fW2 = (const float*)d_in[30]; const float* fb2 = (const float*)d_in[31];
    float* out = (float*)d_out;

    float *px, *ph, *pg, *pt;
    cudaGetSymbolAddress((void**)&px, g_x);
    cudaGetSymbolAddress((void**)&ph, g_h);
    cudaGetSymbolAddress((void**)&pg, g_g);
    cudaGetSymbolAddress((void**)&pt, g_t);

    k_init_scales<<<1, 32>>>();
    k_geom<<<(NE + 255) / 256, 256>>>(pos, src, dst);
    k_triplet<<<(NT + 255) / 256, 256>>>(t_src, t_dst, dst);
    k_nodeinit<<<(NN * 128 + 255) / 256, 256>>>(node_type, emb);
    k_edgeemb<<<(NE * 128 + 255) / 256, 256>>>(eW, eb);

    for (int k = 0; k < 3; k++) {
        k_atoms<<<(NN * 9 + 255) / 256, 256>>>(taW + k * 128 * 9, tab + k * 9);
        k_zero_nb<<<(NE * 9 + 255) / 256, 256>>>();
        k_tripacc<<<(NT + 255) / 256, 256>>>(t_src);
        k_tbond<<<(NE * 128 + 255) / 256, 256>>>(tbW + k * 9 * 128, tbWg + k * 9 * 128);
        k_buildx<<<(NE * 384 + 255) / 256, 256>>>(src, dst);
        for (int br = 0; br < 2; br++) {
            int o384 = (k * 2 + br) * 384 * 128;
            int o128 = (k * 2 + br) * 128 * 128;
            int ob   = (k * 2 + br) * 128;
            gemm(px, W0 + o384, b0 + ob, ph, NE, 384, 128, 0);
            gemm(ph, W1 + o128, b1 + ob, pt, NE, 128, 128, 0);
            gemm(pt, W2 + o128, b2 + ob, ph, NE, 128, 128, 0);
            gemm(px, gW0 + o384, gb0 + ob, pg, NE, 384, 128, 0);
            gemm(pg, gW1 + o128, gb1 + ob, pt, NE, 128, 128, 0);
            gemm(pt, gW2 + o128, gb2 + ob, pg, NE, 128, 128, 1);
            if (br == 0)
                k_combine_edge<<<(NE * 128 + 255) / 256, 256>>>(wt + (k * 2) * 9 * 128);
            else
                k_combine_node<<<(NE * 128 + 255) / 256, 256>>>(wt + (k * 2 + 1) * 9 * 128, dst);
        }
    }
    k_final<<<1, 128>>>(fW0, fb0, fW1, fb1, fW2, fb2, out);
}

// round 2
// speedup vs baseline: 2.0651x; 2.0651x over previous
#include <cuda_runtime.h>
#include <math.h>

#define NN 5000
#define NE 60000
#define NT 400000

// ---------------- scratch (device globals; no allocations allowed) -------------
__device__ float g_bondvec[NE * 3];
__device__ float g_dist[NE];
__device__ float g_rbf[NE * 9];
__device__ float g_cut3[NE];
__device__ float g_tbw[NT * 9];      // three_basis * tw
__device__ int   g_endatom[NT];
__device__ float g_nodefeat[NN * 128];
__device__ float g_edgefeat[NE * 128];
__device__ float g_atoms[NN * 9];
__device__ float g_nb[NE * 9];
__device__ float g_h[NE * 128];
__device__ float g_g[NE * 128];
__device__ float g_t[NE * 128];
__device__ float g_scale[9];

__constant__ float c_roots[9] = {
    3.141592653589793f, 6.283185307179586f, 9.42477796076938f,
    4.493409457909064f, 7.725251836937707f, 10.904121659428899f,
    5.763459196894550f, 9.095011330476355f, 12.322940970566582f};

#define Y00F 0.28209479177387814f
#define Y10F 0.4886025119029199f
#define Y20F 0.31539156525252005f

__device__ __forceinline__ float siluf(float v) { return v / (1.f + expf(-v)); }
__device__ __forceinline__ float sigf(float v)  { return 1.f / (1.f + expf(-v)); }

__device__ __forceinline__ float jlf(int l, float x) {
    float s, c;
    sincosf(x, &s, &c);
    float inv = 1.f / x;
    if (l == 0) return s * inv;
    if (l == 1) return (s * inv - c) * inv;
    return (3.f * inv * inv - 1.f) * s * inv - 3.f * c * inv * inv;
}

__device__ double jld(int l, double x) {
    double s = sin(x), c = cos(x);
    if (l == 0) return s / x;
    if (l == 1) return s / (x * x) - c / x;
    if (l == 2) return (3.0 / (x * x * x) - 1.0 / x) * s - 3.0 * c / (x * x);
    return (15.0 / (x * x * x * x) - 6.0 / (x * x)) * s - (15.0 / (x * x * x) - 1.0 / x) * c;
}

// ---------------- setup kernels ------------------------------------------------
__global__ void k_init_scales() {
    if (threadIdx.x == 0 && blockIdx.x == 0) {
        const double roots[9] = {
            3.141592653589793, 6.283185307179586, 9.42477796076938,
            4.493409457909064, 7.725251836937707, 10.904121659428899,
            5.763459196894550, 9.095011330476355, 12.322940970566582};
        double fac = sqrt(2.0 / 125.0);  // sqrt(2/CUTOFF^3), CUTOFF=5
        for (int l = 0; l < 3; l++)
            for (int n = 0; n < 3; n++) {
                double norm = fabs(jld(l + 1, roots[l * 3 + n]));
                g_scale[l * 3 + n] = (float)(fac / norm);
            }
    }
}

__global__ void k_geom(const float* __restrict__ pos, const int* __restrict__ src,
                       const int* __restrict__ dst) {
    int e = blockIdx.x * blockDim.x + threadIdx.x;
    if (e >= NE) return;
    int s = src[e], d = dst[e];
    float dx = pos[d * 3 + 0] - pos[s * 3 + 0];
    float dy = pos[d * 3 + 1] - pos[s * 3 + 1];
    float dz = pos[d * 3 + 2] - pos[s * 3 + 2];
    float dist = sqrtf(dx * dx + dy * dy + dz * dz + 1e-12f);
    g_bondvec[e * 3 + 0] = dx;
    g_bondvec[e * 3 + 1] = dy;
    g_bondvec[e * 3 + 2] = dz;
    g_dist[e] = dist;
#pragma unroll
    for (int l = 0; l < 3; l++)
#pragma unroll
        for (int n = 0; n < 3; n++)
            g_rbf[e * 9 + l * 3 + n] = jlf(l, dist * c_roots[l * 3 + n] * 0.2f) * g_scale[l * 3 + n];
    float xx = dist * 0.25f;  // /TB_CUTOFF
    float x2 = xx * xx, x3 = x2 * xx;
    g_cut3[e] = 1.f - 6.f * x3 * x2 + 15.f * x2 * x2 - 10.f * x3;
}

// triplet basis: reuse rbf row of t_dst (identical values), no sincos needed
__global__ void k_triplet(const int* __restrict__ t_src, const int* __restrict__ t_dst,
                          const int* __restrict__ dst) {
    int t = blockIdx.x * blockDim.x + threadIdx.x;
    if (t >= NT) return;
    int es = t_src[t], ed = t_dst[t];
    float v1x = g_bondvec[es * 3 + 0], v1y = g_bondvec[es * 3 + 1], v1z = g_bondvec[es * 3 + 2];
    float v2x = g_bondvec[ed * 3 + 0], v2y = g_bondvec[ed * 3 + 1], v2z = g_bondvec[ed * 3 + 2];
    float d1 = g_dist[es], d2 = g_dist[ed];
    float cost = (v1x * v2x + v1y * v2y + v1z * v2z) / (d1 * d2);
    float shf[3];
    shf[0] = Y00F;
    shf[1] = Y10F * cost;
    shf[2] = Y20F * (3.f * cost * cost - 1.f);
    float tw = g_cut3[es] * g_cut3[ed];
#pragma unroll
    for (int l = 0; l < 3; l++)
#pragma unroll
        for (int n = 0; n < 3; n++)
            g_tbw[t * 9 + l * 3 + n] = g_rbf[ed * 9 + l * 3 + n] * shf[l] * tw;
    g_endatom[t] = dst[ed];
}

__global__ void k_nodeinit(const int* __restrict__ node_type, const float* __restrict__ emb) {
    int idx = blockIdx.x * blockDim.x + threadIdx.x;
    if (idx >= NN * 128) return;
    int n = idx >> 7, c = idx & 127;
    g_nodefeat[idx] = emb[node_type[n] * 128 + c];
}

__global__ void k_edgeemb(const float* __restrict__ W, const float* __restrict__ b) {
    int idx = blockIdx.x * blockDim.x + threadIdx.x;
    if (idx >= NE * 128) return;
    int e = idx >> 7, j = idx & 127;
    float acc = b[j];
#pragma unroll
    for (int q = 0; q < 9; q++) acc = fmaf(g_rbf[e * 9 + q], W[q * 128 + j], acc);
    g_edgefeat[idx] = siluf(acc);
}

// ---------------- per-block kernels --------------------------------------------
__global__ void k_atoms(const float* __restrict__ W, const float* __restrict__ b) {
    int idx = blockIdx.x * blockDim.x + threadIdx.x;
    if (idx >= NN * 9) return;
    int n = idx / 9, j = idx % 9;
    float acc = b[j];
    const float* nf = &g_nodefeat[n * 128];
#pragma unroll 8
    for (int i = 0; i < 128; i++) acc = fmaf(nf[i], W[i * 9 + j], acc);
    g_atoms[idx] = sigf(acc);
}

__global__ void k_zero_nb() {
    int idx = blockIdx.x * blockDim.x + threadIdx.x;
    if (idx < NE * 9) g_nb[idx] = 0.f;
}

__global__ void k_tripacc(const int* __restrict__ t_src) {
    int t = blockIdx.x * blockDim.x + threadIdx.x;
    if (t >= NT) return;
    int es = t_src[t];
    int ea = g_endatom[t];
#pragma unroll
    for (int q = 0; q < 9; q++)
        atomicAdd(&g_nb[es * 9 + q], g_tbw[t * 9 + q] * g_atoms[ea * 9 + q]);
}

__global__ void k_tbond(const float* __restrict__ Wb, const float* __restrict__ Wg) {
    int idx = blockIdx.x * blockDim.x + threadIdx.x;
    if (idx >= NE * 128) return;
    int e = idx >> 7, j = idx & 127;
    float s1 = 0.f, s2 = 0.f;
#pragma unroll
    for (int q = 0; q < 9; q++) {
        float nv = g_nb[e * 9 + q];
        s1 = fmaf(nv, Wb[q * 128 + j], s1);
        s2 = fmaf(nv, Wg[q * 128 + j], s2);
    }
    g_edgefeat[idx] += siluf(s1) * sigf(s2);
}

__global__ void k_combine_edge(const float* __restrict__ wt) {
    int idx = blockIdx.x * blockDim.x + threadIdx.x;
    if (idx >= NE * 128) return;
    int e = idx >> 7, j = idx & 127;
    float w = 0.f;
#pragma unroll
    for (int q = 0; q < 9; q++) w = fmaf(g_rbf[e * 9 + q], wt[q * 128 + j], w);
    g_edgefeat[idx] += g_h[idx] * g_g[idx] * w;
}

__global__ void k_combine_node(const float* __restrict__ wt, const int* __restrict__ dst) {
    int idx = blockIdx.x * blockDim.x + threadIdx.x;
    if (idx >= NE * 128) return;
    int e = idx >> 7, j = idx & 127;
    float w = 0.f;
#pragma unroll
    for (int q = 0; q < 9; q++) w = fmaf(g_rbf[e * 9 + q], wt[q * 128 + j], w);
    float m = g_h[idx] * g_g[idx] * w;
    atomicAdd(&g_nodefeat[dst[e] * 128 + j], m);
}

// ---------------- tf32 tensor-core GEMM ----------------------------------------
// C[M,128] = act(A[M,K] @ B[K,128] + bias).  MODE 0: dense A.  MODE 1: gathered
// A = concat(node[src], node[dst], edgefeat) with K=384 (each 32-wide k-tile lies
// entirely inside one 128-wide segment).
#define BM 128
#define BK 32
#define AS_STRIDE 40    // pad 8: fragment loads conflict-free, 16B-aligned rows
#define BS_STRIDE 136   // 128+8: fragment loads conflict-free, 16B-aligned rows

__device__ __forceinline__ unsigned f2tf(float x) {
    unsigned u;
    asm("cvt.rna.tf32.f32 %0, %1;" : "=r"(u) : "f"(x));
    return u;
}

__device__ __forceinline__ void mma_tf32(float* d, const unsigned* a, unsigned b0, unsigned b1) {
    asm volatile(
        "mma.sync.aligned.m16n8k8.row.col.f32.tf32.tf32.f32 "
        "{%0,%1,%2,%3}, {%4,%5,%6,%7}, {%8,%9}, {%0,%1,%2,%3};"
        : "+f"(d[0]), "+f"(d[1]), "+f"(d[2]), "+f"(d[3])
        : "r"(a[0]), "r"(a[1]), "r"(a[2]), "r"(a[3]), "r"(b0), "r"(b1));
}

template <int MODE>
__global__ void __launch_bounds__(256) gemm_tc(
    const float* __restrict__ A,
    const int* __restrict__ src, const int* __restrict__ dst,
    const float* __restrict__ nodef, const float* __restrict__ edgef,
    const float* __restrict__ B, const float* __restrict__ bias,
    float* __restrict__ C, int M, int K, int act) {
    __shared__ unsigned As[BM * AS_STRIDE];
    __shared__ unsigned Bs[BK * BS_STRIDE];
    const int tid = threadIdx.x;
    const int bm = blockIdx.x * BM;
    const int lane = tid & 31, wid = tid >> 5;
    const int wm = (wid & 3) * 32, wn = (wid >> 2) * 64;

    float acc[2][8][4];
#pragma unroll
    for (int i = 0; i < 2; i++)
#pragma unroll
        for (int j = 0; j < 8; j++)
#pragma unroll
            for (int q = 0; q < 4; q++) acc[i][j][q] = 0.f;

    // global-load thread mapping
    const int r0 = tid >> 3;          // A rows r0 + 32*i
    const int c4 = tid & 7;           // A float4 column group
    const int bk0 = tid >> 5;         // B rows bk0 + 8*i
    const int bn4 = tid & 31;         // B float4 column group

    int aoffS[4], aoffD[4], aoffE[4];
    bool valid[4];
#pragma unroll
    for (int i = 0; i < 4; i++) {
        int e = bm + r0 + 32 * i;
        bool v = e < M;
        valid[i] = v;
        if (MODE == 1) {
            aoffS[i] = v ? src[e] * 128 : 0;
            aoffD[i] = v ? dst[e] * 128 : 0;
            aoffE[i] = v ? e * 128 : 0;
        }
    }

    float4 pa[4], pb[4];
    const float4 z4 = make_float4(0.f, 0.f, 0.f, 0.f);

    auto load_tiles = [&](int kt) {
        int k0 = kt * BK;
#pragma unroll
        for (int i = 0; i < 4; i++) {
            if (!valid[i]) { pa[i] = z4; continue; }
            const float* ap;
            if (MODE == 0) {
                int e = bm + r0 + 32 * i;
                ap = A + (size_t)e * K + k0 + c4 * 4;
            } else {
                int seg = k0 >> 7;
                int col = (k0 & 127) + c4 * 4;
                ap = (seg == 0 ? nodef + aoffS[i]
                     : seg == 1 ? nodef + aoffD[i]
                                : edgef + aoffE[i]) + col;
            }
            pa[i] = *(const float4*)ap;
        }
#pragma unroll
        for (int i = 0; i < 4; i++) {
            int kb = k0 + bk0 + 8 * i;
            pb[i] = *(const float4*)(B + (size_t)kb * 128 + bn4 * 4);
        }
    };

    auto store_tiles = [&]() {
#pragma unroll
        for (int i = 0; i < 4; i++) {
            int row = r0 + 32 * i;
            uint4 u;
            u.x = f2tf(pa[i].x); u.y = f2tf(pa[i].y);
            u.z = f2tf(pa[i].z); u.w = f2tf(pa[i].w);
            *(uint4*)&As[row * AS_STRIDE + c4 * 4] = u;
        }
#pragma unroll
        for (int i = 0; i < 4; i++) {
            int kb = bk0 + 8 * i;
            uint4 u;
            u.x = f2tf(pb[i].x); u.y = f2tf(pb[i].y);
            u.z = f2tf(pb[i].z); u.w = f2tf(pb[i].w);
            *(uint4*)&Bs[kb * BS_STRIDE + bn4 * 4] = u;
        }
    };

    const int nk = K / BK;
    load_tiles(0);
    for (int kt = 0; kt < nk; kt++) {
        store_tiles();
        __syncthreads();
        if (kt + 1 < nk) load_tiles(kt + 1);
        // compute on smem tile
#pragma unroll
        for (int ks = 0; ks < 4; ks++) {
            unsigned a[2][4];
            int arow = wm + (lane >> 2);
            int acol = ks * 8 + (lane & 3);
#pragma unroll
            for (int mt = 0; mt < 2; mt++) {
                int rr = arow + mt * 16;
                a[mt][0] = As[rr * AS_STRIDE + acol];
                a[mt][1] = As[(rr + 8) * AS_STRIDE + acol];
                a[mt][2] = As[rr * AS_STRIDE + acol + 4];
                a[mt][3] = As[(rr + 8) * AS_STRIDE + acol + 4];
            }
            int bro = (ks * 8 + (lane & 3)) * BS_STRIDE + wn + (lane >> 2);
#pragma unroll
            for (int nt = 0; nt < 8; nt++) {
                unsigned b0 = Bs[bro + nt * 8];
                unsigned b1 = Bs[bro + 4 * BS_STRIDE + nt * 8];
                mma_tf32(acc[0][nt], a[0], b0, b1);
                mma_tf32(acc[1][nt], a[1], b0, b1);
            }
        }
        __syncthreads();
    }

    // epilogue: bias + activation
#pragma unroll
    for (int mt = 0; mt < 2; mt++) {
        int gm0 = bm + wm + mt * 16 + (lane >> 2);
#pragma unroll
        for (int nt = 0; nt < 8; nt++) {
            int gn = wn + nt * 8 + 2 * (lane & 3);
            float bv0 = bias[gn], bv1 = bias[gn + 1];
            if (gm0 < M) {
                float v0 = acc[mt][nt][0] + bv0;
                float v1 = acc[mt][nt][1] + bv1;
                v0 = (act == 0) ? siluf(v0) : sigf(v0);
                v1 = (act == 0) ? siluf(v1) : sigf(v1);
                *(float2*)(C + (size_t)gm0 * 128 + gn) = make_float2(v0, v1);
            }
            int gm1 = gm0 + 8;
            if (gm1 < M) {
                float v2 = acc[mt][nt][2] + bv0;
                float v3 = acc[mt][nt][3] + bv1;
                v2 = (act == 0) ? siluf(v2) : sigf(v2);
                v3 = (act == 0) ? siluf(v3) : sigf(v3);
                *(float2*)(C + (size_t)gm1 * 128 + gn) = make_float2(v2, v3);
            }
        }
    }
}

// ---------------- final readout ------------------------------------------------
__global__ void k_final(const float* __restrict__ fW0, const float* __restrict__ fb0,
                        const float* __restrict__ fW1, const float* __restrict__ fb1,
                        const float* __restrict__ fW2, const float* __restrict__ fb2,
                        float* __restrict__ out) {
    __shared__ float v[128], h0[128], h1[128], red[128];
    int j = threadIdx.x;
    float s = 0.f;
#pragma unroll 4
    for (int n = 0; n < NN; n++) s += g_nodefeat[n * 128 + j];
    v[j] = s / (float)NN;
    __syncthreads();
    float a = fb0[j];
    for (int i = 0; i < 128; i++) a = fmaf(v[i], fW0[i * 128 + j], a);
    h0[j] = siluf(a);
    __syncthreads();
    a = fb1[j];
    for (int i = 0; i < 128; i++) a = fmaf(h0[i], fW1[i * 128 + j], a);
    h1[j] = siluf(a);
    __syncthreads();
    red[j] = h1[j] * fW2[j];
    __syncthreads();
    for (int st = 64; st > 0; st >>= 1) {
        if (j < st) red[j] += red[j + st];
        __syncthreads();
    }
    if (j == 0) out[0] = red[0] + fb2[0];
}

// ---------------- host ----------------------------------------------------------
#define GEMM_GRID ((NE + BM - 1) / BM)

extern "C" void kernel_launch(void* const* d_in, const int* in_sizes, int n_in,
                              void* d_out, int out_size) {
    const float* pos  = (const float*)d_in[0];
    const int* node_type = (const int*)d_in[1];
    const int* src  = (const int*)d_in[2];
    const int* dst  = (const int*)d_in[3];
    const int* t_src = (const int*)d_in[4];
    const int* t_dst = (const int*)d_in[5];
    const float* emb  = (const float*)d_in[6];
    const float* eW   = (const float*)d_in[7];
    const float* eb   = (const float*)d_in[8];
    const float* taW  = (const float*)d_in[9];
    const float* tab  = (const float*)d_in[10];
    const float* tbW  = (const float*)d_in[11];
    const float* tbWg = (const float*)d_in[12];
    const float* W0 = (const float*)d_in[13];  const float* b0 = (const float*)d_in[14];
    const float* W1 = (const float*)d_in[15];  const float* b1 = (const float*)d_in[16];
    const float* W2 = (const float*)d_in[17];  const float* b2 = (const float*)d_in[18];
    const float* gW0 = (const float*)d_in[19]; const float* gb0 = (const float*)d_in[20];
    const float* gW1 = (const float*)d_in[21]; const float* gb1 = (const float*)d_in[22];
    const float* gW2 = (const float*)d_in[23]; const float* gb2 = (const float*)d_in[24];
    const float* wt = (const float*)d_in[25];
    const float* fW0 = (const float*)d_in[26]; const float* fb0 = (const float*)d_in[27];
    const float* fW1 = (const float*)d_in[28]; const float* fb1 = (const float*)d_in[29];
    const float* fW2 = (const float*)d_in[30]; const float* fb2 = (const float*)d_in[31];
    float* out = (float*)d_out;

    float *pnf, *pef, *ph, *pg, *pt;
    cudaGetSymbolAddress((void**)&pnf, g_nodefeat);
    cudaGetSymbolAddress((void**)&pef, g_edgefeat);
    cudaGetSymbolAddress((void**)&ph, g_h);
    cudaGetSymbolAddress((void**)&pg, g_g);
    cudaGetSymbolAddress((void**)&pt, g_t);

    k_init_scales<<<1, 32>>>();
    k_geom<<<(NE + 255) / 256, 256>>>(pos, src, dst);
    k_triplet<<<(NT + 255) / 256, 256>>>(t_src, t_dst, dst);
    k_nodeinit<<<(NN * 128 + 255) / 256, 256>>>(node_type, emb);
    k_edgeemb<<<(NE * 128 + 255) / 256, 256>>>(eW, eb);

    for (int k = 0; k < 3; k++) {
        k_atoms<<<(NN * 9 + 255) / 256, 256>>>(taW + k * 128 * 9, tab + k * 9);
        k_zero_nb<<<(NE * 9 + 255) / 256, 256>>>();
        k_tripacc<<<(NT + 255) / 256, 256>>>(t_src);
        k_tbond<<<(NE * 128 + 255) / 256, 256>>>(tbW + k * 9 * 128, tbWg + k * 9 * 128);
        for (int br = 0; br < 2; br++) {
            int o384 = (k * 2 + br) * 384 * 128;
            int o128 = (k * 2 + br) * 128 * 128;
            int ob   = (k * 2 + br) * 128;
            // h path
            gemm_tc<1><<<GEMM_GRID, 256>>>(nullptr, src, dst, pnf, pef,
                                           W0 + o384, b0 + ob, ph, NE, 384, 0);
            gemm_tc<0><<<GEMM_GRID, 256>>>(ph, nullptr, nullptr, nullptr, nullptr,
                                           W1 + o128, b1 + ob, pt, NE, 128, 0);
            gemm_tc<0><<<GEMM_GRID, 256>>>(pt, nullptr, nullptr, nullptr, nullptr,
                                           W2 + o128, b2 + ob, ph, NE, 128, 0);
            // g path
            gemm_tc<1><<<GEMM_GRID, 256>>>(nullptr, src, dst, pnf, pef,
                                           gW0 + o384, gb0 + ob, pg, NE, 384, 0);
            gemm_tc<0><<<GEMM_GRID, 256>>>(pg, nullptr, nullptr, nullptr, nullptr,
                                           gW1 + o128, gb1 + ob, pt, NE, 128, 0);
            gemm_tc<0><<<GEMM_GRID, 256>>>(pt, nullptr, nullptr, nullptr, nullptr,
                                           gW2 + o128, gb2 + ob, pg, NE, 128, 1);
            if (br == 0)
                k_combine_edge<<<(NE * 128 + 255) / 256, 256>>>(wt + (k * 2) * 9 * 128);
            else
                k_combine_node<<<(NE * 128 + 255) / 256, 256>>>(wt + (k * 2 + 1) * 9 * 128, dst);
        }
    }
    k_final<<<1, 128>>>(fW0, fb0, fW1, fb1, fW2, fb2, out);
}

// round 3
// speedup vs baseline: 2.0798x; 1.0071x over previous
#include <cuda_runtime.h>
#include <math.h>

#define NN 5000
#define NE 60000
#define NT 400000
#define FUSED_GRID 469            // ceil(60000/128)
#define FUSED_SMEM 181760         // bytes of dynamic smem

// ---------------- scratch (device globals; no allocations allowed) -------------
__device__ float g_bondvec[NE * 3];
__device__ float g_dist[NE];
__device__ float g_rbf[NE * 9];
__device__ float g_cut3[NE];
__device__ float g_tbw[NT * 9];
__device__ int   g_endatom[NT];
__device__ float g_nodefeat[NN * 128];
__device__ float g_edgefeat[NE * 128];
__device__ float g_atoms[NN * 9];
__device__ float g_nb[NE * 9];
__device__ float g_msg[NE * 128];
__device__ float g_scale[9];
__device__ float g_mean[128];

__constant__ float c_roots[9] = {
    3.141592653589793f, 6.283185307179586f, 9.42477796076938f,
    4.493409457909064f, 7.725251836937707f, 10.904121659428899f,
    5.763459196894550f, 9.095011330476355f, 12.322940970566582f};

#define Y00F 0.28209479177387814f
#define Y10F 0.4886025119029199f
#define Y20F 0.31539156525252005f

__device__ __forceinline__ float siluf(float v) { return v / (1.f + expf(-v)); }
__device__ __forceinline__ float sigf(float v)  { return 1.f / (1.f + expf(-v)); }

__device__ __forceinline__ float jlf(int l, float x) {
    float s, c;
    sincosf(x, &s, &c);
    float inv = 1.f / x;
    if (l == 0) return s * inv;
    if (l == 1) return (s * inv - c) * inv;
    return (3.f * inv * inv - 1.f) * s * inv - 3.f * c * inv * inv;
}

__device__ double jld(int l, double x) {
    double s = sin(x), c = cos(x);
    if (l == 0) return s / x;
    if (l == 1) return s / (x * x) - c / x;
    if (l == 2) return (3.0 / (x * x * x) - 1.0 / x) * s - 3.0 * c / (x * x);
    return (15.0 / (x * x * x * x) - 6.0 / (x * x)) * s - (15.0 / (x * x * x) - 1.0 / x) * c;
}

// ---------------- setup kernels ------------------------------------------------
__global__ void k_init_scales() {
    int j = threadIdx.x;
    if (j < 128) g_mean[j] = 0.f;
    if (j == 0) {
        const double roots[9] = {
            3.141592653589793, 6.283185307179586, 9.42477796076938,
            4.493409457909064, 7.725251836937707, 10.904121659428899,
            5.763459196894550, 9.095011330476355, 12.322940970566582};
        double fac = sqrt(2.0 / 125.0);
        for (int l = 0; l < 3; l++)
            for (int n = 0; n < 3; n++)
                g_scale[l * 3 + n] = (float)(fac / fabs(jld(l + 1, roots[l * 3 + n])));
    }
}

__global__ void k_geom(const float* __restrict__ pos, const int* __restrict__ src,
                       const int* __restrict__ dst) {
    int e = blockIdx.x * blockDim.x + threadIdx.x;
    if (e >= NE) return;
    int s = src[e], d = dst[e];
    float dx = pos[d * 3 + 0] - pos[s * 3 + 0];
    float dy = pos[d * 3 + 1] - pos[s * 3 + 1];
    float dz = pos[d * 3 + 2] - pos[s * 3 + 2];
    float dist = sqrtf(dx * dx + dy * dy + dz * dz + 1e-12f);
    g_bondvec[e * 3 + 0] = dx;
    g_bondvec[e * 3 + 1] = dy;
    g_bondvec[e * 3 + 2] = dz;
    g_dist[e] = dist;
#pragma unroll
    for (int l = 0; l < 3; l++)
#pragma unroll
        for (int n = 0; n < 3; n++)
            g_rbf[e * 9 + l * 3 + n] = jlf(l, dist * c_roots[l * 3 + n] * 0.2f) * g_scale[l * 3 + n];
    float xx = dist * 0.25f;
    float x2 = xx * xx, x3 = x2 * xx;
    g_cut3[e] = 1.f - 6.f * x3 * x2 + 15.f * x2 * x2 - 10.f * x3;
}

__global__ void k_triplet(const int* __restrict__ t_src, const int* __restrict__ t_dst,
                          const int* __restrict__ dst) {
    int t = blockIdx.x * blockDim.x + threadIdx.x;
    if (t >= NT) return;
    int es = t_src[t], ed = t_dst[t];
    float v1x = g_bondvec[es * 3 + 0], v1y = g_bondvec[es * 3 + 1], v1z = g_bondvec[es * 3 + 2];
    float v2x = g_bondvec[ed * 3 + 0], v2y = g_bondvec[ed * 3 + 1], v2z = g_bondvec[ed * 3 + 2];
    float cost = (v1x * v2x + v1y * v2y + v1z * v2z) / (g_dist[es] * g_dist[ed]);
    float shf[3];
    shf[0] = Y00F;
    shf[1] = Y10F * cost;
    shf[2] = Y20F * (3.f * cost * cost - 1.f);
    float tw = g_cut3[es] * g_cut3[ed];
#pragma unroll
    for (int l = 0; l < 3; l++)
#pragma unroll
        for (int n = 0; n < 3; n++)
            g_tbw[t * 9 + l * 3 + n] = g_rbf[ed * 9 + l * 3 + n] * shf[l] * tw;
    g_endatom[t] = dst[ed];
}

__global__ void k_nodeinit(const int* __restrict__ node_type, const float* __restrict__ emb) {
    int idx = blockIdx.x * blockDim.x + threadIdx.x;
    if (idx >= NN * 128) return;
    int n = idx >> 7, c = idx & 127;
    g_nodefeat[idx] = emb[node_type[n] * 128 + c];
}

__global__ void k_edgeemb(const float* __restrict__ W, const float* __restrict__ b) {
    int idx = blockIdx.x * blockDim.x + threadIdx.x;
    if (idx >= NE * 128) return;
    int e = idx >> 7, j = idx & 127;
    float acc = b[j];
#pragma unroll
    for (int q = 0; q < 9; q++) acc = fmaf(g_rbf[e * 9 + q], W[q * 128 + j], acc);
    g_edgefeat[idx] = siluf(acc);
}

// ---------------- per-block glue kernels ---------------------------------------
__global__ void k_atoms(const float* __restrict__ W, const float* __restrict__ b) {
    int idx = blockIdx.x * blockDim.x + threadIdx.x;
    if (idx >= NN * 9) return;
    int n = idx / 9, j = idx % 9;
    float acc = b[j];
    const float* nf = &g_nodefeat[n * 128];
#pragma unroll 8
    for (int i = 0; i < 128; i++) acc = fmaf(nf[i], W[i * 9 + j], acc);
    g_atoms[idx] = sigf(acc);
}

__global__ void k_zero_nb() {
    int idx = blockIdx.x * blockDim.x + threadIdx.x;
    if (idx < NE * 9) g_nb[idx] = 0.f;
}

__global__ void k_tripacc(const int* __restrict__ t_src) {
    int t = blockIdx.x * blockDim.x + threadIdx.x;
    if (t >= NT) return;
    int es = t_src[t];
    int ea = g_endatom[t];
#pragma unroll
    for (int q = 0; q < 9; q++)
        atomicAdd(&g_nb[es * 9 + q], g_tbw[t * 9 + q] * g_atoms[ea * 9 + q]);
}

__global__ void k_tbond(const float* __restrict__ Wb, const float* __restrict__ Wg) {
    int idx = blockIdx.x * blockDim.x + threadIdx.x;
    if (idx >= NE * 128) return;
    int e = idx >> 7, j = idx & 127;
    float s1 = 0.f, s2 = 0.f;
#pragma unroll
    for (int q = 0; q < 9; q++) {
        float nv = g_nb[e * 9 + q];
        s1 = fmaf(nv, Wb[q * 128 + j], s1);
        s2 = fmaf(nv, Wg[q * 128 + j], s2);
    }
    g_edgefeat[idx] += siluf(s1) * sigf(s2);
}

__global__ void k_scatter(const int* __restrict__ dst) {
    int idx = blockIdx.x * blockDim.x + threadIdx.x;
    if (idx >= NE * 128) return;
    int e = idx >> 7, j = idx & 127;
    atomicAdd(&g_nodefeat[dst[e] * 128 + j], g_msg[idx]);
}

// ---------------- fused gated-MLP megakernel -----------------------------------
__device__ __forceinline__ unsigned f2tf(float x) {
    unsigned u;
    asm("cvt.rna.tf32.f32 %0, %1;" : "=r"(u) : "f"(x));
    return u;
}

__device__ __forceinline__ void mma_tf32(float* d, const unsigned* a, unsigned b0, unsigned b1) {
    asm volatile(
        "mma.sync.aligned.m16n8k8.row.col.f32.tf32.tf32.f32 "
        "{%0,%1,%2,%3}, {%4,%5,%6,%7}, {%8,%9}, {%0,%1,%2,%3};"
        : "+f"(d[0]), "+f"(d[1]), "+f"(d[2]), "+f"(d[3])
        : "r"(a[0]), "r"(a[1]), "r"(a[2]), "r"(a[3]), "r"(b0), "r"(b1));
}

// smem layout (unsigned units):
//   sH  : 128*136   h activations (tf32 bits; final layer: fp32 bits)
//   sG  : 128*136   g activations
//   sB  : 32*136    current weight k-tile
//   sA  : 128*40    layer-0 gathered A k-tile
//   swt : 9*128     wt matrix (float bits)
template <int BR>
__global__ void __launch_bounds__(256) fused_conv(
    const int* __restrict__ src, const int* __restrict__ dst,
    const float* __restrict__ nodef, float* __restrict__ edgef,
    const float* __restrict__ Wh0, const float* __restrict__ bh0,
    const float* __restrict__ Wh1, const float* __restrict__ bh1,
    const float* __restrict__ Wh2, const float* __restrict__ bh2,
    const float* __restrict__ Wg0, const float* __restrict__ bg0,
    const float* __restrict__ Wg1, const float* __restrict__ bg1,
    const float* __restrict__ Wg2, const float* __restrict__ bg2,
    const float* __restrict__ wt, const float* __restrict__ rbf,
    float* __restrict__ msg) {
    extern __shared__ unsigned smem_u[];
    unsigned* sH = smem_u;
    unsigned* sG = smem_u + 128 * 136;
    unsigned* sB = smem_u + 2 * 128 * 136;
    unsigned* sA = sB + 32 * 136;
    float* swt = (float*)(sA + 128 * 40);

    const int tid = threadIdx.x;
    const int lane = tid & 31, wid = tid >> 5;
    const int wm = (wid & 3) * 32, wn = (wid >> 2) * 64;
    const int bm = blockIdx.x * 128;

    for (int i = tid; i < 9 * 128; i += 256) swt[i] = wt[i];

    const int r0 = tid >> 3, c4 = tid & 7;     // A-load mapping
    const int bk0 = tid >> 5, bn4 = tid & 31;  // B-load mapping

    int aoffS[4], aoffD[4], aoffE[4];
    bool valid[4];
#pragma unroll
    for (int i = 0; i < 4; i++) {
        int e = bm + r0 + 32 * i;
        valid[i] = e < NE;
        int ee = valid[i] ? e : 0;
        aoffS[i] = src[ee] * 128;
        aoffD[i] = dst[ee] * 128;
        aoffE[i] = ee * 128;
    }

    float acc[2][8][4];
    float4 pa[4], pb[4];
    const float4 z4 = make_float4(0.f, 0.f, 0.f, 0.f);

    auto zero_acc = [&] {
#pragma unroll
        for (int i = 0; i < 2; i++)
#pragma unroll
            for (int j = 0; j < 8; j++)
#pragma unroll
                for (int q = 0; q < 4; q++) acc[i][j][q] = 0.f;
    };
    auto load_gather = [&](int kt) {
        int k0 = kt * 32;
        int seg = k0 >> 7;
        int col = (k0 & 127) + c4 * 4;
#pragma unroll
        for (int i = 0; i < 4; i++) {
            const float* bp = (seg == 0 ? nodef + aoffS[i]
                               : seg == 1 ? nodef + aoffD[i]
                                          : edgef + aoffE[i]);
            pa[i] = valid[i] ? *(const float4*)(bp + col) : z4;
        }
    };
    auto load_B = [&](const float* Bw, int kt) {
        int k0 = kt * 32;
#pragma unroll
        for (int i = 0; i < 4; i++)
            pb[i] = *(const float4*)(Bw + (size_t)(k0 + bk0 + 8 * i) * 128 + bn4 * 4);
    };
    auto store_A = [&] {
#pragma unroll
        for (int i = 0; i < 4; i++) {
            uint4 u;
            u.x = f2tf(pa[i].x); u.y = f2tf(pa[i].y);
            u.z = f2tf(pa[i].z); u.w = f2tf(pa[i].w);
            *(uint4*)&sA[(r0 + 32 * i) * 40 + c4 * 4] = u;
        }
    };
    auto store_B = [&] {
#pragma unroll
        for (int i = 0; i < 4; i++) {
            uint4 u;
            u.x = f2tf(pb[i].x); u.y = f2tf(pb[i].y);
            u.z = f2tf(pb[i].z); u.w = f2tf(pb[i].w);
            *(uint4*)&sB[(bk0 + 8 * i) * 136 + bn4 * 4] = u;
        }
    };
    auto compute = [&](const unsigned* aptr, int astr, int kbase) {
#pragma unroll
        for (int ks = 0; ks < 4; ks++) {
            unsigned a[2][4];
            int arow = wm + (lane >> 2);
            int acol = kbase + ks * 8 + (lane & 3);
#pragma unroll
            for (int mt = 0; mt < 2; mt++) {
                int rr = arow + mt * 16;
                a[mt][0] = aptr[rr * astr + acol];
                a[mt][1] = aptr[(rr + 8) * astr + acol];
                a[mt][2] = aptr[rr * astr + acol + 4];
                a[mt][3] = aptr[(rr + 8) * astr + acol + 4];
            }
            int bro = (ks * 8 + (lane & 3)) * 136 + wn + (lane >> 2);
#pragma unroll
            for (int nt = 0; nt < 8; nt++) {
                unsigned b0 = sB[bro + nt * 8];
                unsigned b1 = sB[bro + 4 * 136 + nt * 8];
                mma_tf32(acc[0][nt], a[0], b0, b1);
                mma_tf32(acc[1][nt], a[1], b0, b1);
            }
        }
    };
    auto write_act = [&](const float* bias, unsigned* sAct, bool as_f32) {
#pragma unroll
        for (int mt = 0; mt < 2; mt++) {
            int gm0 = wm + mt * 16 + (lane >> 2);
            int gn0 = wn + 2 * (lane & 3);
#pragma unroll
            for (int nt = 0; nt < 8; nt++) {
                int gn = gn0 + nt * 8;
                float bv0 = bias[gn], bv1 = bias[gn + 1];
                float v0 = siluf(acc[mt][nt][0] + bv0);
                float v1 = siluf(acc[mt][nt][1] + bv1);
                float v2 = siluf(acc[mt][nt][2] + bv0);
                float v3 = siluf(acc[mt][nt][3] + bv1);
                if (as_f32) {
                    sAct[gm0 * 136 + gn] = __float_as_uint(v0);
                    sAct[gm0 * 136 + gn + 1] = __float_as_uint(v1);
                    sAct[(gm0 + 8) * 136 + gn] = __float_as_uint(v2);
                    sAct[(gm0 + 8) * 136 + gn + 1] = __float_as_uint(v3);
                } else {
                    sAct[gm0 * 136 + gn] = f2tf(v0);
                    sAct[gm0 * 136 + gn + 1] = f2tf(v1);
                    sAct[(gm0 + 8) * 136 + gn] = f2tf(v2);
                    sAct[(gm0 + 8) * 136 + gn + 1] = f2tf(v3);
                }
            }
        }
    };

    for (int chain = 0; chain < 2; chain++) {
        unsigned* sAct = chain ? sG : sH;
        const float* B0 = chain ? Wg0 : Wh0;
        const float* B1 = chain ? Wg1 : Wh1;
        const float* B2 = chain ? Wg2 : Wh2;
        const float* bb0 = chain ? bg0 : bh0;
        const float* bb1 = chain ? bg1 : bh1;

        // --- layer 0: K=384, gathered A ---
        zero_acc();
        load_gather(0);
        load_B(B0, 0);
        for (int kt = 0; kt < 12; kt++) {
            store_A();
            store_B();
            __syncthreads();
            if (kt < 11) { load_gather(kt + 1); load_B(B0, kt + 1); }
            compute(sA, 40, 0);
            __syncthreads();
        }
        write_act(bb0, sAct, false);
        __syncthreads();

        // --- layer 1: K=128, A in smem ---
        zero_acc();
        load_B(B1, 0);
        for (int kt = 0; kt < 4; kt++) {
            store_B();
            __syncthreads();
            if (kt < 3) load_B(B1, kt + 1);
            compute(sAct, 136, kt * 32);
            __syncthreads();
        }
        write_act(bb1, sAct, false);
        __syncthreads();

        // --- layer 2: K=128, A in smem ---
        zero_acc();
        load_B(B2, 0);
        for (int kt = 0; kt < 4; kt++) {
            store_B();
            __syncthreads();
            if (kt < 3) load_B(B2, kt + 1);
            compute(sAct, 136, kt * 32);
            __syncthreads();
        }
        if (chain == 0) {
            write_act(bh2, sH, true);  // silu(h2) stored fp32 for epilogue
            __syncthreads();
        }
        // chain 1: pre-activation g2 stays in acc
    }

    // --- epilogue: val = silu(h2) * sigmoid(g2+gb2) * (rbf @ wt) ---
    float rb[2][2][9];
    bool ev[2][2];
    int gml_[2][2];
#pragma unroll
    for (int mt = 0; mt < 2; mt++)
#pragma unroll
        for (int hf = 0; hf < 2; hf++) {
            int gm = wm + mt * 16 + (lane >> 2) + hf * 8;
            int e = bm + gm;
            gml_[mt][hf] = gm;
            ev[mt][hf] = e < NE;
            if (ev[mt][hf]) {
#pragma unroll
                for (int q = 0; q < 9; q++) rb[mt][hf][q] = rbf[e * 9 + q];
            }
        }
#pragma unroll
    for (int nt = 0; nt < 8; nt++) {
#pragma unroll
        for (int c = 0; c < 2; c++) {
            int gn = wn + nt * 8 + 2 * (lane & 3) + c;
            float wcol[9];
#pragma unroll
            for (int q = 0; q < 9; q++) wcol[q] = swt[q * 128 + gn];
            float gbv = bg2[gn];
#pragma unroll
            for (int mt = 0; mt < 2; mt++)
#pragma unroll
                for (int hf = 0; hf < 2; hf++) {
                    if (!ev[mt][hf]) continue;
                    float wtw = 0.f;
#pragma unroll
                    for (int q = 0; q < 9; q++) wtw = fmaf(rb[mt][hf][q], wcol[q], wtw);
                    float gv = sigf(acc[mt][nt][hf * 2 + c] + gbv);
                    float hv = __uint_as_float(sH[gml_[mt][hf] * 136 + gn]);
                    float val = hv * gv * wtw;
                    int e = bm + gml_[mt][hf];
                    if (BR == 0) edgef[e * 128 + gn] += val;
                    else         msg[e * 128 + gn] = val;
                }
        }
    }
}

// ---------------- readout -------------------------------------------------------
__global__ void k_mean() {
    int j = threadIdx.x;
    int b = blockIdx.x;
    float s = 0.f;
    for (int n = b * 125; n < b * 125 + 125; n++) s += g_nodefeat[n * 128 + j];
    atomicAdd(&g_mean[j], s);
}

__global__ void k_final(const float* __restrict__ fW0, const float* __restrict__ fb0,
                        const float* __restrict__ fW1, const float* __restrict__ fb1,
                        const float* __restrict__ fW2, const float* __restrict__ fb2,
                        float* __restrict__ out) {
    __shared__ float v[128], h0[128], h1[128], red[128];
    int j = threadIdx.x;
    v[j] = g_mean[j] / (float)NN;
    __syncthreads();
    float a = fb0[j];
    for (int i = 0; i < 128; i++) a = fmaf(v[i], fW0[i * 128 + j], a);
    h0[j] = siluf(a);
    __syncthreads();
    a = fb1[j];
    for (int i = 0; i < 128; i++) a = fmaf(h0[i], fW1[i * 128 + j], a);
    h1[j] = siluf(a);
    __syncthreads();
    red[j] = h1[j] * fW2[j];
    __syncthreads();
    for (int st = 64; st > 0; st >>= 1) {
        if (j < st) red[j] += red[j + st];
        __syncthreads();
    }
    if (j == 0) out[0] = red[0] + fb2[0];
}

// ---------------- host ----------------------------------------------------------
extern "C" void kernel_launch(void* const* d_in, const int* in_sizes, int n_in,
                              void* d_out, int out_size) {
    const float* pos  = (const float*)d_in[0];
    const int* node_type = (const int*)d_in[1];
    const int* src  = (const int*)d_in[2];
    const int* dst  = (const int*)d_in[3];
    const int* t_src = (const int*)d_in[4];
    const int* t_dst = (const int*)d_in[5];
    const float* emb  = (const float*)d_in[6];
    const float* eW   = (const float*)d_in[7];
    const float* eb   = (const float*)d_in[8];
    const float* taW  = (const float*)d_in[9];
    const float* tab  = (const float*)d_in[10];
    const float* tbW  = (const float*)d_in[11];
    const float* tbWg = (const float*)d_in[12];
    const float* W0 = (const float*)d_in[13];  const float* b0 = (const float*)d_in[14];
    const float* W1 = (const float*)d_in[15];  const float* b1 = (const float*)d_in[16];
    const float* W2 = (const float*)d_in[17];  const float* b2 = (const float*)d_in[18];
    const float* gW0 = (const float*)d_in[19]; const float* gb0 = (const float*)d_in[20];
    const float* gW1 = (const float*)d_in[21]; const float* gb1 = (const float*)d_in[22];
    const float* gW2 = (const float*)d_in[23]; const float* gb2 = (const float*)d_in[24];
    const float* wt = (const float*)d_in[25];
    const float* fW0 = (const float*)d_in[26]; const float* fb0 = (const float*)d_in[27];
    const float* fW1 = (const float*)d_in[28]; const float* fb1 = (const float*)d_in[29];
    const float* fW2 = (const float*)d_in[30]; const float* fb2 = (const float*)d_in[31];
    float* out = (float*)d_out;

    float *pnf, *pef, *pmsg, *prbf;
    cudaGetSymbolAddress((void**)&pnf, g_nodefeat);
    cudaGetSymbolAddress((void**)&pef, g_edgefeat);
    cudaGetSymbolAddress((void**)&pmsg, g_msg);
    cudaGetSymbolAddress((void**)&prbf, g_rbf);

    cudaFuncSetAttribute(fused_conv<0>, cudaFuncAttributeMaxDynamicSharedMemorySize, FUSED_SMEM);
    cudaFuncSetAttribute(fused_conv<1>, cudaFuncAttributeMaxDynamicSharedMemorySize, FUSED_SMEM);

    k_init_scales<<<1, 128>>>();
    k_geom<<<(NE + 255) / 256, 256>>>(pos, src, dst);
    k_triplet<<<(NT + 255) / 256, 256>>>(t_src, t_dst, dst);
    k_nodeinit<<<(NN * 128 + 255) / 256, 256>>>(node_type, emb);
    k_edgeemb<<<(NE * 128 + 255) / 256, 256>>>(eW, eb);

    for (int k = 0; k < 3; k++) {
        k_atoms<<<(NN * 9 + 255) / 256, 256>>>(taW + k * 128 * 9, tab + k * 9);
        k_zero_nb<<<(NE * 9 + 255) / 256, 256>>>();
        k_tripacc<<<(NT + 255) / 256, 256>>>(t_src);
        k_tbond<<<(NE * 128 + 255) / 256, 256>>>(tbW + k * 9 * 128, tbWg + k * 9 * 128);
        for (int br = 0; br < 2; br++) {
            int o384 = (k * 2 + br) * 384 * 128;
            int o128 = (k * 2 + br) * 128 * 128;
            int ob   = (k * 2 + br) * 128;
            int owt  = (k * 2 + br) * 9 * 128;
            if (br == 0)
                fused_conv<0><<<FUSED_GRID, 256, FUSED_SMEM>>>(
                    src, dst, pnf, pef,
                    W0 + o384, b0 + ob, W1 + o128, b1 + ob, W2 + o128, b2 + ob,
                    gW0 + o384, gb0 + ob, gW1 + o128, gb1 + ob, gW2 + o128, gb2 + ob,
                    wt + owt, prbf, pmsg);
            else {
                fused_conv<1><<<FUSED_GRID, 256, FUSED_SMEM>>>(
                    src, dst, pnf, pef,
                    W0 + o384, b0 + ob, W1 + o128, b1 + ob, W2 + o128, b2 + ob,
                    gW0 + o384, gb0 + ob, gW1 + o128, gb1 + ob, gW2 + o128, gb2 + ob,
                    wt + owt, prbf, pmsg);
                k_scatter<<<(NE * 128 + 255) / 256, 256>>>(dst);
            }
        }
    }
    k_mean<<<40, 128>>>();
    k_final<<<1, 128>>>(fW0, fb0, fW1, fb1, fW2, fb2, out);
}